// round 3
// baseline (speedup 1.0000x reference)
#include <cuda_runtime.h>
#include <cuda_bf16.h>
#include <cstdint>

// ---------------- problem constants ----------------
#define N0v 1000000
#define N1v 102400
#define N2v 10240
#define N3v 1024
#define E0v 1024000
#define E1v 102400
#define E2v 10240
#define DINv 128
#define DHv  256
#define DOUTv 40

// ---------------- device scratch ----------------
__device__ float g_aggr0[N1v * DINv];
__device__ float g_cnt0[N1v];
__device__ float g_h1[(long)N1v * DHv];
__device__ float g_aggr1[N2v * DHv];
__device__ float g_cnt1[N2v];
__device__ float g_h2[N2v * DHv];
__device__ float g_aggr2[N3v * DHv];
__device__ float g_cnt2[N3v];

// ---------------- helpers ----------------
__device__ __forceinline__ uint32_t smem_u32(const void* p) {
    uint32_t a;
    asm("{ .reg .u64 t; cvta.to.shared.u64 t, %1; cvt.u32.u64 %0, t; }"
        : "=r"(a) : "l"(p));
    return a;
}
__device__ __forceinline__ void ldmatrix_x4(uint32_t& r0, uint32_t& r1,
                                            uint32_t& r2, uint32_t& r3,
                                            uint32_t addr) {
    asm volatile("ldmatrix.sync.aligned.m8n8.x4.shared.b16 {%0,%1,%2,%3}, [%4];"
                 : "=r"(r0), "=r"(r1), "=r"(r2), "=r"(r3) : "r"(addr));
}
__device__ __forceinline__ void ldmatrix_x2(uint32_t& r0, uint32_t& r1,
                                            uint32_t addr) {
    asm volatile("ldmatrix.sync.aligned.m8n8.x2.shared.b16 {%0,%1}, [%2];"
                 : "=r"(r0), "=r"(r1) : "r"(addr));
}
__device__ __forceinline__ void mma_bf16(float& c0, float& c1, float& c2, float& c3,
                                         uint32_t a0, uint32_t a1, uint32_t a2,
                                         uint32_t a3, uint32_t b0, uint32_t b1) {
    asm volatile(
        "mma.sync.aligned.m16n8k16.row.col.f32.bf16.bf16.f32 "
        "{%0,%1,%2,%3},{%4,%5,%6,%7},{%8,%9},{%0,%1,%2,%3};"
        : "+f"(c0), "+f"(c1), "+f"(c2), "+f"(c3)
        : "r"(a0), "r"(a1), "r"(a2), "r"(a3), "r"(b0), "r"(b1));
}
__device__ __forceinline__ uint32_t pack_bf16_hi(float x, float y) {
    __nv_bfloat162 p{__float2bfloat16(x), __float2bfloat16(y)};
    return *reinterpret_cast<uint32_t*>(&p);
}
__device__ __forceinline__ uint32_t pack_bf16_lo(float x, float y, uint32_t hi) {
    __nv_bfloat162 h = *reinterpret_cast<__nv_bfloat162*>(&hi);
    __nv_bfloat162 p{__float2bfloat16(x - __bfloat162float(h.x)),
                     __float2bfloat16(y - __bfloat162float(h.y))};
    return *reinterpret_cast<uint32_t*>(&p);
}

// ---------------- zero / recip ----------------
__global__ void zero_kernel(float4* __restrict__ p, int n4) {
    int i = blockIdx.x * blockDim.x + threadIdx.x;
    if (i < n4) p[i] = make_float4(0.f, 0.f, 0.f, 0.f);
}
__global__ void recip_kernel(float* __restrict__ c, int n) {
    int i = blockIdx.x * blockDim.x + threadIdx.x;
    if (i < n) c[i] = 1.0f / fmaxf(c[i], 1.0f);
}

// ---------------- edge aggregation (warp per edge, red.v4) ----------------
__device__ __forceinline__ void red_add_v4(float* p, float4 v) {
    asm volatile("red.global.add.v4.f32 [%0], {%1, %2, %3, %4};"
                 :: "l"(p), "f"(v.x), "f"(v.y), "f"(v.z), "f"(v.w) : "memory");
}
template <int V4>
__global__ void edge_agg_kernel(const float* __restrict__ H,
                                const int* __restrict__ src,
                                const int* __restrict__ dst,
                                float* __restrict__ aggr,
                                float* __restrict__ cnt, int E) {
    int w = (blockIdx.x * blockDim.x + threadIdx.x) >> 5;
    int lane = threadIdx.x & 31;
    if (w >= E) return;
    int s = __ldg(&src[w]);
    int d = __ldg(&dst[w]);
    const float4* sp = reinterpret_cast<const float4*>(H) + (long)s * V4;
    float* dp = aggr + (long)d * (V4 * 4);
#pragma unroll
    for (int it = 0; it < V4 / 32; ++it) {
        int i = lane + it * 32;
        red_add_v4(dp + i * 4, sp[i]);
    }
    if (lane == 0) atomicAdd(cnt + d, 1.0f);
}

// ---------------- MMA dual GEMM with bf16 split ----------------
// C[128 x 128-tile] = act( (Aagg*rn) @ Wl + Atgt @ Wr + bias )
// grid = (M/128, Ntot/128); 256 threads = 8 warps (2 x 4).
#define SKB 40   // padded halfword stride of a BK=32 tile row

template <int K>
__global__ __launch_bounds__(256)
void mma_gemm_kernel(const float* __restrict__ Aagg,
                     const float* __restrict__ rn,
                     const float* __restrict__ Atgt,
                     const float* __restrict__ Wl,
                     const float* __restrict__ Wr,
                     const float* __restrict__ bias,
                     float* __restrict__ C,
                     int Ntot, int relu) {
    __shared__ __align__(16) __nv_bfloat16 sAh[128 * SKB];
    __shared__ __align__(16) __nv_bfloat16 sAl[128 * SKB];
    __shared__ __align__(16) __nv_bfloat16 sBh[128 * SKB];
    __shared__ __align__(16) __nv_bfloat16 sBl[128 * SKB];

    const int tid = threadIdx.x;
    const int wid = tid >> 5;
    const int lane = tid & 31;
    const int warpR = wid & 1;        // 0..1 -> 64-row slab
    const int warpC = wid >> 1;       // 0..3 -> 32-col slab
    const int rowBase = blockIdx.x * 128;
    const int colBase = blockIdx.y * 128;

    // A load mapping: row = tid/2, half = tid&1 (16 floats)
    const int aRow = tid >> 1;
    const int aHalf = (tid & 1) * 16;
    const float scale0 = rn[rowBase + aRow];

    // ldmatrix lane addressing (element offsets within tile)
    const uint32_t aBaseH = smem_u32(sAh);
    const uint32_t aBaseL = smem_u32(sAl);
    const uint32_t bBaseH = smem_u32(sBh);
    const uint32_t bBaseL = smem_u32(sBl);
    const int aLdRow = warpR * 64 + (lane & 15);
    const int aLdCol = (lane >> 4) * 8;
    const int bLdRow = warpC * 32 + (lane & 7);
    const int bLdCol = ((lane >> 3) & 1) * 8;

    float acc[4][4][4];
#pragma unroll
    for (int i = 0; i < 4; ++i)
#pragma unroll
        for (int j = 0; j < 4; ++j)
#pragma unroll
            for (int v = 0; v < 4; ++v) acc[i][j][v] = 0.f;

    for (int pass = 0; pass < 2; ++pass) {
        const float* A = pass ? Atgt : Aagg;
        const float* W = pass ? Wr : Wl;
        const float scale = pass ? 1.0f : scale0;

        for (int kt = 0; kt < K / 32; ++kt) {
            __syncthreads();
            // ---- A tile: 128 rows x 32 k (fp32) -> bf16 hi/lo ----
            {
                const float* ap = A + (long)(rowBase + aRow) * K + kt * 32 + aHalf;
#pragma unroll
                for (int q = 0; q < 4; ++q) {
                    float4 v = *(const float4*)(ap + q * 4);
                    v.x *= scale; v.y *= scale; v.z *= scale; v.w *= scale;
                    uint32_t h0 = pack_bf16_hi(v.x, v.y);
                    uint32_t h1 = pack_bf16_hi(v.z, v.w);
                    uint32_t l0 = pack_bf16_lo(v.x, v.y, h0);
                    uint32_t l1 = pack_bf16_lo(v.z, v.w, h1);
                    int off = aRow * SKB + aHalf + q * 4;
                    *(uint2*)(sAh + off) = make_uint2(h0, h1);
                    *(uint2*)(sAl + off) = make_uint2(l0, l1);
                }
            }
            // ---- W tile: 32 k-rows x 128 n -> sB[n][k] transposed hi/lo ----
            {
                int n4 = (lane & 31) * 4 % 128;         // 0,4,...,124
                int n0 = (tid & 31) * 4;                // 0..124 step 4
                int kk0 = tid >> 5;                     // 0..7
                (void)n4;
#pragma unroll
                for (int r = 0; r < 4; ++r) {
                    int kk = kt * 32 + kk0 + r * 8;
                    float4 v = *(const float4*)(W + (long)kk * Ntot + colBase + n0);
                    int kcol = kk0 + r * 8;
                    float vv[4] = {v.x, v.y, v.z, v.w};
#pragma unroll
                    for (int j = 0; j < 4; ++j) {
                        __nv_bfloat16 h = __float2bfloat16(vv[j]);
                        __nv_bfloat16 l = __float2bfloat16(vv[j] - __bfloat162float(h));
                        sBh[(n0 + j) * SKB + kcol] = h;
                        sBl[(n0 + j) * SKB + kcol] = l;
                    }
                }
            }
            __syncthreads();

            // ---- compute: 2 k-steps of 16 ----
#pragma unroll
            for (int ks = 0; ks < 2; ++ks) {
                uint32_t ah[4][4], al[4][4], bh[4][2], bl[4][2];
#pragma unroll
                for (int mf = 0; mf < 4; ++mf) {
                    uint32_t off = (uint32_t)((aLdRow + mf * 16) * SKB
                                              + ks * 16 + aLdCol) * 2;
                    ldmatrix_x4(ah[mf][0], ah[mf][1], ah[mf][2], ah[mf][3], aBaseH + off);
                    ldmatrix_x4(al[mf][0], al[mf][1], al[mf][2], al[mf][3], aBaseL + off);
                }
#pragma unroll
                for (int nf = 0; nf < 4; ++nf) {
                    uint32_t off = (uint32_t)((bLdRow + nf * 8) * SKB
                                              + ks * 16 + bLdCol) * 2;
                    ldmatrix_x2(bh[nf][0], bh[nf][1], bBaseH + off);
                    ldmatrix_x2(bl[nf][0], bl[nf][1], bBaseL + off);
                }
#pragma unroll
                for (int mf = 0; mf < 4; ++mf)
#pragma unroll
                    for (int nf = 0; nf < 4; ++nf) {
                        float* c = acc[mf][nf];
                        mma_bf16(c[0], c[1], c[2], c[3],
                                 ah[mf][0], ah[mf][1], ah[mf][2], ah[mf][3],
                                 bh[nf][0], bh[nf][1]);
                        mma_bf16(c[0], c[1], c[2], c[3],
                                 ah[mf][0], ah[mf][1], ah[mf][2], ah[mf][3],
                                 bl[nf][0], bl[nf][1]);
                        mma_bf16(c[0], c[1], c[2], c[3],
                                 al[mf][0], al[mf][1], al[mf][2], al[mf][3],
                                 bh[nf][0], bh[nf][1]);
                    }
            }
        }
    }

    // ---- epilogue ----
    const int gr = lane >> 2;           // 0..7
    const int gc = (lane & 3) * 2;      // 0,2,4,6
#pragma unroll
    for (int mf = 0; mf < 4; ++mf) {
#pragma unroll
        for (int nf = 0; nf < 4; ++nf) {
            int col = colBase + warpC * 32 + nf * 8 + gc;
            float b0 = bias[col], b1 = bias[col + 1];
            int row0 = rowBase + warpR * 64 + mf * 16 + gr;
            float* c = acc[mf][nf];
            float2 o0 = make_float2(c[0] + b0, c[1] + b1);
            float2 o1 = make_float2(c[2] + b0, c[3] + b1);
            if (relu) {
                o0.x = fmaxf(o0.x, 0.f); o0.y = fmaxf(o0.y, 0.f);
                o1.x = fmaxf(o1.x, 0.f); o1.y = fmaxf(o1.y, 0.f);
            }
            *(float2*)(C + (long)row0 * Ntot + col) = o0;
            *(float2*)(C + (long)(row0 + 8) * Ntot + col) = o1;
        }
    }
}

// ---------------- layer 2: dual GEMV + log_softmax ----------------
__global__ void layer2_kernel(const float* __restrict__ aggr2,
                              const float* __restrict__ rn2,
                              const float* __restrict__ h2,
                              const float* __restrict__ Wl2,
                              const float* __restrict__ Wr2,
                              const float* __restrict__ b2,
                              float* __restrict__ out) {
    __shared__ float a[2 * DHv];
    __shared__ float c[DOUTv];
    __shared__ float lse;

    int row = blockIdx.x;
    int tid = threadIdx.x;
    float invc = rn2[row];
    a[tid] = aggr2[(long)row * DHv + tid] * invc;
    a[DHv + tid] = h2[(long)row * DHv + tid];
    __syncthreads();

    if (tid < DOUTv) {
        float s = b2[tid];
#pragma unroll 8
        for (int k = 0; k < DHv; ++k)
            s = fmaf(a[k], __ldg(&Wl2[k * DOUTv + tid]), s);
#pragma unroll 8
        for (int k = 0; k < DHv; ++k)
            s = fmaf(a[DHv + k], __ldg(&Wr2[k * DOUTv + tid]), s);
        c[tid] = s;
    }
    __syncthreads();

    if (tid == 0) {
        float m = c[0];
#pragma unroll
        for (int j = 1; j < DOUTv; ++j) m = fmaxf(m, c[j]);
        float sum = 0.f;
#pragma unroll
        for (int j = 0; j < DOUTv; ++j) sum += expf(c[j] - m);
        lse = m + logf(sum);
    }
    __syncthreads();

    if (tid < DOUTv) out[(long)row * DOUTv + tid] = c[tid] - lse;
}

// ---------------- host launcher ----------------
extern "C" void kernel_launch(void* const* d_in, const int* in_sizes, int n_in,
                              void* d_out, int out_size) {
    const float* x   = (const float*)d_in[0];
    const int* src0  = (const int*)d_in[1];
    const int* dst0  = (const int*)d_in[2];
    const int* src1  = (const int*)d_in[3];
    const int* dst1  = (const int*)d_in[4];
    const int* src2  = (const int*)d_in[5];
    const int* dst2  = (const int*)d_in[6];
    const float* Wl0 = (const float*)d_in[7];
    const float* bl0 = (const float*)d_in[8];
    const float* Wr0 = (const float*)d_in[9];
    const float* Wl1 = (const float*)d_in[10];
    const float* bl1 = (const float*)d_in[11];
    const float* Wr1 = (const float*)d_in[12];
    const float* Wl2 = (const float*)d_in[13];
    const float* bl2 = (const float*)d_in[14];
    const float* Wr2 = (const float*)d_in[15];
    float* out = (float*)d_out;

    float *aggr0, *cnt0, *h1, *aggr1, *cnt1, *h2, *aggr2, *cnt2;
    cudaGetSymbolAddress((void**)&aggr0, g_aggr0);
    cudaGetSymbolAddress((void**)&cnt0,  g_cnt0);
    cudaGetSymbolAddress((void**)&h1,    g_h1);
    cudaGetSymbolAddress((void**)&aggr1, g_aggr1);
    cudaGetSymbolAddress((void**)&cnt1,  g_cnt1);
    cudaGetSymbolAddress((void**)&h2,    g_h2);
    cudaGetSymbolAddress((void**)&aggr2, g_aggr2);
    cudaGetSymbolAddress((void**)&cnt2,  g_cnt2);

    auto zero = [](float* p, long n) {
        int n4 = (int)(n / 4);
        zero_kernel<<<(n4 + 255) / 256, 256>>>((float4*)p, n4);
    };
    zero(aggr0, (long)N1v * DINv);
    zero(cnt0, N1v);
    zero(aggr1, (long)N2v * DHv);
    zero(cnt1, N2v);
    zero(aggr2, (long)N3v * DHv);
    zero(cnt2, N3v);

    // ----- layer 0 -----
    edge_agg_kernel<32><<<E0v / 8, 256>>>(x, src0, dst0, aggr0, cnt0, E0v);
    recip_kernel<<<(N1v + 255) / 256, 256>>>(cnt0, N1v);
    mma_gemm_kernel<128><<<dim3(N1v / 128, 2), 256>>>(
        aggr0, cnt0, x, Wl0, Wr0, bl0, h1, DHv, 1);

    // ----- layer 1 -----
    edge_agg_kernel<64><<<E1v / 8, 256>>>(h1, src1, dst1, aggr1, cnt1, E1v);
    recip_kernel<<<(N2v + 255) / 256, 256>>>(cnt1, N2v);
    mma_gemm_kernel<256><<<dim3(N2v / 128, 2), 256>>>(
        aggr1, cnt1, h1, Wl1, Wr1, bl1, h2, DHv, 1);

    // ----- layer 2 + log_softmax -----
    edge_agg_kernel<64><<<E2v / 8, 256>>>(h2, src2, dst2, aggr2, cnt2, E2v);
    recip_kernel<<<(N3v + 255) / 256, 256>>>(cnt2, N3v);
    layer2_kernel<<<N3v, 256>>>(aggr2, cnt2, h2, Wl2, Wr2, bl2, out);

    (void)in_sizes; (void)n_in; (void)out_size;
}

// round 4
// speedup vs baseline: 1.5244x; 1.5244x over previous
#include <cuda_runtime.h>
#include <cuda_bf16.h>
#include <cstdint>

// ---------------- problem constants ----------------
#define N0v 1000000
#define N1v 102400
#define N2v 10240
#define N3v 1024
#define E0v 1024000
#define E1v 102400
#define E2v 10240
#define DINv 128
#define DHv  256
#define DOUTv 40

// ---------------- device scratch ----------------
__device__ float g_aggr0[N1v * DINv];
__device__ float g_cnt0[N1v];
__device__ float g_h1[(long)N1v * DHv];
__device__ float g_aggr1[N2v * DHv];
__device__ float g_cnt1[N2v];
__device__ float g_h2[N2v * DHv];
__device__ float g_aggr2[N3v * DHv];
__device__ float g_cnt2[N3v];
// bf16 staging: A2 = [aggr*rn | tgt]  (max 102400x256), W2T = [Wl;Wr]^T (max 256x512)
__device__ __nv_bfloat16 g_Ahi[(long)N1v * 256];
__device__ __nv_bfloat16 g_Alo[(long)N1v * 256];
__device__ __nv_bfloat16 g_Whi[256 * 512];
__device__ __nv_bfloat16 g_Wlo[256 * 512];

// ---------------- asm helpers ----------------
__device__ __forceinline__ uint32_t smem_u32(const void* p) {
    uint32_t a;
    asm("{ .reg .u64 t; cvta.to.shared.u64 t, %1; cvt.u32.u64 %0, t; }"
        : "=r"(a) : "l"(p));
    return a;
}
__device__ __forceinline__ void ldmatrix_x4(uint32_t& r0, uint32_t& r1,
                                            uint32_t& r2, uint32_t& r3,
                                            uint32_t addr) {
    asm volatile("ldmatrix.sync.aligned.m8n8.x4.shared.b16 {%0,%1,%2,%3}, [%4];"
                 : "=r"(r0), "=r"(r1), "=r"(r2), "=r"(r3) : "r"(addr));
}
__device__ __forceinline__ void mma_bf16(float& c0, float& c1, float& c2, float& c3,
                                         uint32_t a0, uint32_t a1, uint32_t a2,
                                         uint32_t a3, uint32_t b0, uint32_t b1) {
    asm volatile(
        "mma.sync.aligned.m16n8k16.row.col.f32.bf16.bf16.f32 "
        "{%0,%1,%2,%3},{%4,%5,%6,%7},{%8,%9},{%0,%1,%2,%3};"
        : "+f"(c0), "+f"(c1), "+f"(c2), "+f"(c3)
        : "r"(a0), "r"(a1), "r"(a2), "r"(a3), "r"(b0), "r"(b1));
}
__device__ __forceinline__ void cp16(uint32_t dst, const void* src) {
    asm volatile("cp.async.cg.shared.global [%0], [%1], 16;"
                 :: "r"(dst), "l"(src));
}
#define CP_COMMIT() asm volatile("cp.async.commit_group;")
#define CP_WAIT0()  asm volatile("cp.async.wait_group 0;")
#define CP_WAIT1()  asm volatile("cp.async.wait_group 1;")

__device__ __forceinline__ void red_add_v4(float* p, float4 v) {
    asm volatile("red.global.add.v4.f32 [%0], {%1, %2, %3, %4};"
                 :: "l"(p), "f"(v.x), "f"(v.y), "f"(v.z), "f"(v.w) : "memory");
}

// ---------------- zero ----------------
__global__ void zero_kernel(float4* __restrict__ p, int n4) {
    int i = blockIdx.x * blockDim.x + threadIdx.x;
    if (i < n4) p[i] = make_float4(0.f, 0.f, 0.f, 0.f);
}

// ---------------- edge aggregation (warp per edge, red.v4) ----------------
template <int V4>
__global__ void edge_agg_kernel(const float* __restrict__ H,
                                const int* __restrict__ src,
                                const int* __restrict__ dst,
                                float* __restrict__ aggr,
                                float* __restrict__ cnt, int E) {
    int w = (blockIdx.x * blockDim.x + threadIdx.x) >> 5;
    int lane = threadIdx.x & 31;
    if (w >= E) return;
    int s = __ldg(&src[w]);
    int d = __ldg(&dst[w]);
    const float4* sp = reinterpret_cast<const float4*>(H) + (long)s * V4;
    float* dp = aggr + (long)d * (V4 * 4);
#pragma unroll
    for (int it = 0; it < V4 / 32; ++it) {
        int i = lane + it * 32;
        red_add_v4(dp + i * 4, sp[i]);
    }
    if (lane == 0) atomicAdd(cnt + d, 1.0f);
}

// ---------------- bf16 split helpers ----------------
__device__ __forceinline__ void split2(float x, float y,
                                       uint32_t& hi, uint32_t& lo) {
    __nv_bfloat16 hx = __float2bfloat16(x);
    __nv_bfloat16 hy = __float2bfloat16(y);
    __nv_bfloat162 hp{hx, hy};
    __nv_bfloat162 lp{__float2bfloat16(x - __bfloat162float(hx)),
                      __float2bfloat16(y - __bfloat162float(hy))};
    hi = *reinterpret_cast<uint32_t*>(&hp);
    lo = *reinterpret_cast<uint32_t*>(&lp);
}

// ---------------- A2 = [aggr*rn | tgt] -> bf16 hi/lo ----------------
// K2 = 2*KA. Thread handles 4 floats. grid = M*K2/4/256.
template <int KA>
__global__ void convert_A_kernel(const float* __restrict__ aggr,
                                 const float* __restrict__ cnt,
                                 const float* __restrict__ tgt,
                                 __nv_bfloat16* __restrict__ Ahi,
                                 __nv_bfloat16* __restrict__ Alo) {
    constexpr int C4 = KA / 2;   // float4 slots per row (K2/4)
    long idx = (long)blockIdx.x * blockDim.x + threadIdx.x;
    int r = (int)(idx / C4);
    int col = (int)(idx % C4) * 4;
    float4 v;
    if (col < KA) {
        float s = 1.0f / fmaxf(__ldg(&cnt[r]), 1.0f);
        v = *(const float4*)(aggr + (long)r * KA + col);
        v.x *= s; v.y *= s; v.z *= s; v.w *= s;
    } else {
        v = *(const float4*)(tgt + (long)r * KA + (col - KA));
    }
    uint32_t h0, l0, h1, l1;
    split2(v.x, v.y, h0, l0);
    split2(v.z, v.w, h1, l1);
    long o = (long)r * (2 * KA) + col;
    *(uint2*)(Ahi + o) = make_uint2(h0, h1);
    *(uint2*)(Alo + o) = make_uint2(l0, l1);
}

// ---------------- W2T[n][k2] = (k2<KA ? Wl[k2][n] : Wr[k2-KA][n]) ----------
__global__ void convert_W_kernel(const float* __restrict__ Wl,
                                 const float* __restrict__ Wr,
                                 __nv_bfloat16* __restrict__ Whi,
                                 __nv_bfloat16* __restrict__ Wlo,
                                 int KA, int N) {
    int idx = blockIdx.x * blockDim.x + threadIdx.x;   // over N * 2KA
    int n = idx % N;
    int k2 = idx / N;
    float w = (k2 < KA) ? __ldg(&Wl[(long)k2 * N + n])
                        : __ldg(&Wr[(long)(k2 - KA) * N + n]);
    __nv_bfloat16 h = __float2bfloat16(w);
    __nv_bfloat16 l = __float2bfloat16(w - __bfloat162float(h));
    Whi[(long)n * (2 * KA) + k2] = h;
    Wlo[(long)n * (2 * KA) + k2] = l;
}

// ---------------- bf16-split GEMM: C = act(A2 @ W2T^T + bias) --------------
// 128x128 CTA tile, BK=32, 8 warps (2x4), cp.async double buffer.
// smem layout (halfword units): stage*20480 + {A: sp*5120 + r*40 + k,
//                                              B: 10240 + sp*5120 + n*40 + k}
template <int K2>
__global__ __launch_bounds__(256, 1)
void mma_gemm2_kernel(const __nv_bfloat16* __restrict__ Ahi,
                      const __nv_bfloat16* __restrict__ Alo,
                      const __nv_bfloat16* __restrict__ Whi,
                      const __nv_bfloat16* __restrict__ Wlo,
                      const float* __restrict__ bias,
                      float* __restrict__ C,
                      int Ntot, int relu) {
    constexpr int NT = K2 / 32;
    extern __shared__ __align__(16) __nv_bfloat16 sm[];
    const uint32_t smBase = smem_u32(sm);

    const int tid = threadIdx.x;
    const int lane = tid & 31;
    const int wid = tid >> 5;
    const int warpR = wid & 1;
    const int warpC = wid >> 1;
    const int rowBase = blockIdx.x * 128;
    const int colBase = blockIdx.y * 128;

    // cp.async mapping: thread -> (row r, 32B chunk)
    const int cpRow = tid >> 1;
    const int cpOff = (tid & 1) * 32;   // byte offset within 64B row segment

    // ldmatrix addressing
    const int aRow = warpR * 64 + (lane & 15);
    const int aCol = (lane >> 4) * 8;
    const int bRow = warpC * 32 + (lane & 7) + ((lane >> 4) << 3);
    const int bCol = ((lane >> 3) & 1) * 8;
    const uint32_t aAddr0 = smBase + (uint32_t)aRow * 80 + (uint32_t)aCol * 2;
    const uint32_t bAddr0 = smBase + 20480u + (uint32_t)bRow * 80 + (uint32_t)bCol * 2;

    float acc[4][4][4];
#pragma unroll
    for (int i = 0; i < 4; ++i)
#pragma unroll
        for (int j = 0; j < 4; ++j)
#pragma unroll
            for (int v = 0; v < 4; ++v) acc[i][j][v] = 0.f;

    auto issue = [&](int s, int kt) {
        const uint32_t base = smBase + (uint32_t)s * 40960u;
#pragma unroll
        for (int sp = 0; sp < 2; ++sp) {
            const __nv_bfloat16* a = (sp ? Alo : Ahi)
                + (long)(rowBase + cpRow) * K2 + kt * 32;
            uint32_t dA = base + (uint32_t)sp * 10240u + (uint32_t)cpRow * 80 + cpOff;
            cp16(dA, (const char*)a + cpOff);
            cp16(dA + 16, (const char*)a + cpOff + 16);
            const __nv_bfloat16* b = (sp ? Wlo : Whi)
                + (long)(colBase + cpRow) * K2 + kt * 32;
            uint32_t dB = base + 20480u + (uint32_t)sp * 10240u
                          + (uint32_t)cpRow * 80 + cpOff;
            cp16(dB, (const char*)b + cpOff);
            cp16(dB + 16, (const char*)b + cpOff + 16);
        }
    };

    issue(0, 0);
    CP_COMMIT();

    for (int kt = 0; kt < NT; ++kt) {
        const int s = kt & 1;
        if (kt + 1 < NT) {
            issue(s ^ 1, kt + 1);
            CP_COMMIT();
            CP_WAIT1();
        } else {
            CP_WAIT0();
        }
        __syncthreads();

        const uint32_t stA = aAddr0 + (uint32_t)s * 40960u;
        const uint32_t stB = bAddr0 + (uint32_t)s * 40960u;
#pragma unroll
        for (int ks = 0; ks < 2; ++ks) {
            const uint32_t ksOff = (uint32_t)ks * 32;
            uint32_t ah[4][4], al[4][4], bh[4][2], bl[4][2];
#pragma unroll
            for (int mf = 0; mf < 4; ++mf) {
                uint32_t ad = stA + (uint32_t)mf * 1280 + ksOff;
                ldmatrix_x4(ah[mf][0], ah[mf][1], ah[mf][2], ah[mf][3], ad);
                ldmatrix_x4(al[mf][0], al[mf][1], al[mf][2], al[mf][3], ad + 10240u);
            }
#pragma unroll
            for (int nfp = 0; nfp < 2; ++nfp) {
                uint32_t bd = stB + (uint32_t)nfp * 1280 + ksOff;
                ldmatrix_x4(bh[nfp * 2][0], bh[nfp * 2][1],
                            bh[nfp * 2 + 1][0], bh[nfp * 2 + 1][1], bd);
                ldmatrix_x4(bl[nfp * 2][0], bl[nfp * 2][1],
                            bl[nfp * 2 + 1][0], bl[nfp * 2 + 1][1], bd + 10240u);
            }
#pragma unroll
            for (int mf = 0; mf < 4; ++mf)
#pragma unroll
                for (int nf = 0; nf < 4; ++nf) {
                    float* c = acc[mf][nf];
                    mma_bf16(c[0], c[1], c[2], c[3],
                             ah[mf][0], ah[mf][1], ah[mf][2], ah[mf][3],
                             bh[nf][0], bh[nf][1]);
                    mma_bf16(c[0], c[1], c[2], c[3],
                             ah[mf][0], ah[mf][1], ah[mf][2], ah[mf][3],
                             bl[nf][0], bl[nf][1]);
                    mma_bf16(c[0], c[1], c[2], c[3],
                             al[mf][0], al[mf][1], al[mf][2], al[mf][3],
                             bh[nf][0], bh[nf][1]);
                }
        }
        __syncthreads();
    }

    // ---- epilogue ----
    const int gr = lane >> 2;
    const int gc = (lane & 3) * 2;
#pragma unroll
    for (int mf = 0; mf < 4; ++mf) {
#pragma unroll
        for (int nf = 0; nf < 4; ++nf) {
            int col = colBase + warpC * 32 + nf * 8 + gc;
            float b0 = bias[col], b1 = bias[col + 1];
            int row0 = rowBase + warpR * 64 + mf * 16 + gr;
            float* c = acc[mf][nf];
            float2 o0 = make_float2(c[0] + b0, c[1] + b1);
            float2 o1 = make_float2(c[2] + b0, c[3] + b1);
            if (relu) {
                o0.x = fmaxf(o0.x, 0.f); o0.y = fmaxf(o0.y, 0.f);
                o1.x = fmaxf(o1.x, 0.f); o1.y = fmaxf(o1.y, 0.f);
            }
            *(float2*)(C + (long)row0 * Ntot + col) = o0;
            *(float2*)(C + (long)(row0 + 8) * Ntot + col) = o1;
        }
    }
}

// ---------------- layer 2: dual GEMV + log_softmax ----------------
__global__ void layer2_kernel(const float* __restrict__ aggr2,
                              const float* __restrict__ cnt2,
                              const float* __restrict__ h2,
                              const float* __restrict__ Wl2,
                              const float* __restrict__ Wr2,
                              const float* __restrict__ b2,
                              float* __restrict__ out) {
    __shared__ float a[2 * DHv];
    __shared__ float c[DOUTv];
    __shared__ float lse;

    int row = blockIdx.x;
    int tid = threadIdx.x;
    float invc = 1.0f / fmaxf(cnt2[row], 1.0f);
    a[tid] = aggr2[(long)row * DHv + tid] * invc;
    a[DHv + tid] = h2[(long)row * DHv + tid];
    __syncthreads();

    if (tid < DOUTv) {
        float s = b2[tid];
#pragma unroll 8
        for (int k = 0; k < DHv; ++k)
            s = fmaf(a[k], __ldg(&Wl2[k * DOUTv + tid]), s);
#pragma unroll 8
        for (int k = 0; k < DHv; ++k)
            s = fmaf(a[DHv + k], __ldg(&Wr2[k * DOUTv + tid]), s);
        c[tid] = s;
    }
    __syncthreads();

    if (tid == 0) {
        float m = c[0];
#pragma unroll
        for (int j = 1; j < DOUTv; ++j) m = fmaxf(m, c[j]);
        float sum = 0.f;
#pragma unroll
        for (int j = 0; j < DOUTv; ++j) sum += expf(c[j] - m);
        lse = m + logf(sum);
    }
    __syncthreads();

    if (tid < DOUTv) out[(long)row * DOUTv + tid] = c[tid] - lse;
}

// ---------------- host launcher ----------------
extern "C" void kernel_launch(void* const* d_in, const int* in_sizes, int n_in,
                              void* d_out, int out_size) {
    const float* x   = (const float*)d_in[0];
    const int* src0  = (const int*)d_in[1];
    const int* dst0  = (const int*)d_in[2];
    const int* src1  = (const int*)d_in[3];
    const int* dst1  = (const int*)d_in[4];
    const int* src2  = (const int*)d_in[5];
    const int* dst2  = (const int*)d_in[6];
    const float* Wl0 = (const float*)d_in[7];
    const float* bl0 = (const float*)d_in[8];
    const float* Wr0 = (const float*)d_in[9];
    const float* Wl1 = (const float*)d_in[10];
    const float* bl1 = (const float*)d_in[11];
    const float* Wr1 = (const float*)d_in[12];
    const float* Wl2 = (const float*)d_in[13];
    const float* bl2 = (const float*)d_in[14];
    const float* Wr2 = (const float*)d_in[15];
    float* out = (float*)d_out;

    float *aggr0, *cnt0, *h1, *aggr1, *cnt1, *h2, *aggr2, *cnt2;
    __nv_bfloat16 *Ahi, *Alo, *Whi, *Wlo;
    cudaGetSymbolAddress((void**)&aggr0, g_aggr0);
    cudaGetSymbolAddress((void**)&cnt0,  g_cnt0);
    cudaGetSymbolAddress((void**)&h1,    g_h1);
    cudaGetSymbolAddress((void**)&aggr1, g_aggr1);
    cudaGetSymbolAddress((void**)&cnt1,  g_cnt1);
    cudaGetSymbolAddress((void**)&h2,    g_h2);
    cudaGetSymbolAddress((void**)&aggr2, g_aggr2);
    cudaGetSymbolAddress((void**)&cnt2,  g_cnt2);
    cudaGetSymbolAddress((void**)&Ahi,   g_Ahi);
    cudaGetSymbolAddress((void**)&Alo,   g_Alo);
    cudaGetSymbolAddress((void**)&Whi,   g_Whi);
    cudaGetSymbolAddress((void**)&Wlo,   g_Wlo);

    const int smemG = 81920;
    cudaFuncSetAttribute(mma_gemm2_kernel<256>,
                         cudaFuncAttributeMaxDynamicSharedMemorySize, smemG);
    cudaFuncSetAttribute(mma_gemm2_kernel<512>,
                         cudaFuncAttributeMaxDynamicSharedMemorySize, smemG);

    auto zero = [](float* p, long n) {
        int n4 = (int)(n / 4);
        zero_kernel<<<(n4 + 255) / 256, 256>>>((float4*)p, n4);
    };

    // ----- layer 0 -----  (launch order tuned so launch #6 = L0 GEMM for ncu)
    zero(aggr0, (long)N1v * DINv);                                        // 1
    zero(cnt0, N1v);                                                      // 2
    convert_W_kernel<<<(256 * 256) / 256, 256>>>(Wl0, Wr0, Whi, Wlo,
                                                 DINv, DHv);              // 3
    edge_agg_kernel<32><<<E0v / 8, 256>>>(x, src0, dst0, aggr0, cnt0, E0v); // 4
    convert_A_kernel<DINv><<<(int)(((long)N1v * 256 / 4) / 256), 256>>>(
        aggr0, cnt0, x, Ahi, Alo);                                        // 5
    mma_gemm2_kernel<256><<<dim3(N1v / 128, 2), 256, smemG>>>(
        Ahi, Alo, Whi, Wlo, bl0, h1, DHv, 1);                             // 6

    // ----- layer 1 -----
    zero(aggr1, (long)N2v * DHv);
    zero(cnt1, N2v);
    convert_W_kernel<<<(256 * 512) / 256, 256>>>(Wl1, Wr1, Whi, Wlo,
                                                 DHv, DHv);
    edge_agg_kernel<64><<<E1v / 8, 256>>>(h1, src1, dst1, aggr1, cnt1, E1v);
    convert_A_kernel<DHv><<<(int)(((long)N2v * 512 / 4) / 256), 256>>>(
        aggr1, cnt1, h1, Ahi, Alo);
    mma_gemm2_kernel<512><<<dim3(N2v / 128, 2), 256, smemG>>>(
        Ahi, Alo, Whi, Wlo, bl1, h2, DHv, 1);

    // ----- layer 2 + log_softmax -----
    zero(aggr2, (long)N3v * DHv);
    zero(cnt2, N3v);
    edge_agg_kernel<64><<<E2v / 8, 256>>>(h2, src2, dst2, aggr2, cnt2, E2v);
    layer2_kernel<<<N3v, 256>>>(aggr2, cnt2, h2, Wl2, Wr2, bl2, out);

    (void)in_sizes; (void)n_in; (void)out_size;
}

// round 5
// speedup vs baseline: 1.8109x; 1.1880x over previous
#include <cuda_runtime.h>
#include <cuda_bf16.h>
#include <cstdint>

// ---------------- problem constants ----------------
#define N0v 1000000
#define N1v 102400
#define N2v 10240
#define N3v 1024
#define E0v 1024000
#define E1v 102400
#define E2v 10240
#define DINv 128
#define DHv  256
#define DOUTv 40

// ---------------- device scratch ----------------
__device__ float g_aggr0[N1v * DINv];
__device__ float g_cnt0[N1v];
__device__ float g_h1[(long)N1v * DHv];
__device__ float g_aggr1[N2v * DHv];
__device__ float g_cnt1[N2v];
__device__ float g_h2[N2v * DHv];
__device__ float g_aggr2[N3v * DHv];
__device__ float g_cnt2[N3v];
__device__ __nv_bfloat16 g_Ahi[(long)N1v * 256];
__device__ __nv_bfloat16 g_Alo[(long)N1v * 256];
__device__ __nv_bfloat16 g_Whi[256 * 512];
__device__ __nv_bfloat16 g_Wlo[256 * 512];

// ---------------- asm helpers ----------------
__device__ __forceinline__ uint32_t smem_u32(const void* p) {
    uint32_t a;
    asm("{ .reg .u64 t; cvta.to.shared.u64 t, %1; cvt.u32.u64 %0, t; }"
        : "=r"(a) : "l"(p));
    return a;
}
__device__ __forceinline__ void ldmatrix_x4(uint32_t& r0, uint32_t& r1,
                                            uint32_t& r2, uint32_t& r3,
                                            uint32_t addr) {
    asm volatile("ldmatrix.sync.aligned.m8n8.x4.shared.b16 {%0,%1,%2,%3}, [%4];"
                 : "=r"(r0), "=r"(r1), "=r"(r2), "=r"(r3) : "r"(addr));
}
__device__ __forceinline__ void mma_bf16(float& c0, float& c1, float& c2, float& c3,
                                         uint32_t a0, uint32_t a1, uint32_t a2,
                                         uint32_t a3, uint32_t b0, uint32_t b1) {
    asm volatile(
        "mma.sync.aligned.m16n8k16.row.col.f32.bf16.bf16.f32 "
        "{%0,%1,%2,%3},{%4,%5,%6,%7},{%8,%9},{%0,%1,%2,%3};"
        : "+f"(c0), "+f"(c1), "+f"(c2), "+f"(c3)
        : "r"(a0), "r"(a1), "r"(a2), "r"(a3), "r"(b0), "r"(b1));
}
__device__ __forceinline__ void cp16(uint32_t dst, const void* src) {
    asm volatile("cp.async.cg.shared.global [%0], [%1], 16;"
                 :: "r"(dst), "l"(src));
}
#define CP_COMMIT() asm volatile("cp.async.commit_group;")
#define CP_WAIT0()  asm volatile("cp.async.wait_group 0;")
#define CP_WAIT1()  asm volatile("cp.async.wait_group 1;")

__device__ __forceinline__ void red_add_v4(float* p, float4 v) {
    asm volatile("red.global.add.v4.f32 [%0], {%1, %2, %3, %4};"
                 :: "l"(p), "f"(v.x), "f"(v.y), "f"(v.z), "f"(v.w) : "memory");
}

// ---------------- zero ----------------
__global__ void zero_kernel(float4* __restrict__ p, int n4) {
    int i = blockIdx.x * blockDim.x + threadIdx.x;
    if (i < n4) p[i] = make_float4(0.f, 0.f, 0.f, 0.f);
}

// ---------------- edge aggregation: 4 edges per warp, batched gathers ------
// V4 = row width in float4 (32 for 128-d, 64 for 256-d). EPW edges per warp.
template <int V4, int EPW>
__global__ void edge_agg_kernel(const float* __restrict__ H,
                                const int* __restrict__ src,
                                const int* __restrict__ dst,
                                float* __restrict__ aggr,
                                float* __restrict__ cnt, int E) {
    constexpr int J = V4 / 32;
    int w = (blockIdx.x * blockDim.x + threadIdx.x) >> 5;
    int lane = threadIdx.x & 31;
    long e0 = (long)w * EPW;
    if (e0 >= E) return;

    int sv = 0, dv = 0;
    if (lane < EPW) {
        sv = __ldg(&src[e0 + lane]);
        dv = __ldg(&dst[e0 + lane]);
    }

    // front-batch ALL gathers (MLP = EPW*J per lane), evict-first loads
    float4 vals[EPW][J];
    int dIdx[EPW];
#pragma unroll
    for (int i = 0; i < EPW; ++i) {
        int s = __shfl_sync(0xffffffffu, sv, i);
        dIdx[i] = __shfl_sync(0xffffffffu, dv, i);
        const float4* sp = reinterpret_cast<const float4*>(H) + (long)s * V4;
#pragma unroll
        for (int j = 0; j < J; ++j)
            vals[i][j] = __ldcs(&sp[lane + j * 32]);
    }
#pragma unroll
    for (int i = 0; i < EPW; ++i) {
        float* dp = aggr + (long)dIdx[i] * (V4 * 4);
#pragma unroll
        for (int j = 0; j < J; ++j)
            red_add_v4(dp + (lane + j * 32) * 4, vals[i][j]);
    }
    if (lane < EPW) atomicAdd(cnt + dv, 1.0f);
}

// ---------------- bf16 split helpers ----------------
__device__ __forceinline__ void split2(float x, float y,
                                       uint32_t& hi, uint32_t& lo) {
    __nv_bfloat16 hx = __float2bfloat16(x);
    __nv_bfloat16 hy = __float2bfloat16(y);
    __nv_bfloat162 hp{hx, hy};
    __nv_bfloat162 lp{__float2bfloat16(x - __bfloat162float(hx)),
                      __float2bfloat16(y - __bfloat162float(hy))};
    hi = *reinterpret_cast<uint32_t*>(&hp);
    lo = *reinterpret_cast<uint32_t*>(&lp);
}

// ---------------- A2 = [aggr*rn | tgt] -> bf16 hi/lo ----------------
template <int KA>
__global__ void convert_A_kernel(const float* __restrict__ aggr,
                                 const float* __restrict__ cnt,
                                 const float* __restrict__ tgt,
                                 __nv_bfloat16* __restrict__ Ahi,
                                 __nv_bfloat16* __restrict__ Alo) {
    constexpr int C4 = KA / 2;
    long idx = (long)blockIdx.x * blockDim.x + threadIdx.x;
    int r = (int)(idx / C4);
    int col = (int)(idx % C4) * 4;
    float4 v;
    if (col < KA) {
        float s = 1.0f / fmaxf(__ldg(&cnt[r]), 1.0f);
        v = *(const float4*)(aggr + (long)r * KA + col);
        v.x *= s; v.y *= s; v.z *= s; v.w *= s;
    } else {
        v = *(const float4*)(tgt + (long)r * KA + (col - KA));
    }
    uint32_t h0, l0, h1, l1;
    split2(v.x, v.y, h0, l0);
    split2(v.z, v.w, h1, l1);
    long o = (long)r * (2 * KA) + col;
    *(uint2*)(Ahi + o) = make_uint2(h0, h1);
    *(uint2*)(Alo + o) = make_uint2(l0, l1);
}

// ---------------- W2T[n][k2] ----------------
__global__ void convert_W_kernel(const float* __restrict__ Wl,
                                 const float* __restrict__ Wr,
                                 __nv_bfloat16* __restrict__ Whi,
                                 __nv_bfloat16* __restrict__ Wlo,
                                 int KA, int N) {
    int idx = blockIdx.x * blockDim.x + threadIdx.x;
    int n = idx % N;
    int k2 = idx / N;
    float w = (k2 < KA) ? __ldg(&Wl[(long)k2 * N + n])
                        : __ldg(&Wr[(long)(k2 - KA) * N + n]);
    __nv_bfloat16 h = __float2bfloat16(w);
    __nv_bfloat16 l = __float2bfloat16(w - __bfloat162float(h));
    Whi[(long)n * (2 * KA) + k2] = h;
    Wlo[(long)n * (2 * KA) + k2] = l;
}

// ---------------- bf16-split GEMM (128x128 tile, cp.async x2, 2 CTA/SM) ----
template <int K2>
__global__ __launch_bounds__(256, 2)
void mma_gemm2_kernel(const __nv_bfloat16* __restrict__ Ahi,
                      const __nv_bfloat16* __restrict__ Alo,
                      const __nv_bfloat16* __restrict__ Whi,
                      const __nv_bfloat16* __restrict__ Wlo,
                      const float* __restrict__ bias,
                      float* __restrict__ C,
                      int Ntot, int relu) {
    constexpr int NT = K2 / 32;
    extern __shared__ __align__(16) __nv_bfloat16 sm[];
    const uint32_t smBase = smem_u32(sm);

    const int tid = threadIdx.x;
    const int lane = tid & 31;
    const int wid = tid >> 5;
    const int warpR = wid & 1;
    const int warpC = wid >> 1;
    const int rowBase = blockIdx.x * 128;
    const int colBase = blockIdx.y * 128;

    const int cpRow = tid >> 1;
    const int cpOff = (tid & 1) * 32;

    const int aRow = warpR * 64 + (lane & 15);
    const int aCol = (lane >> 4) * 8;
    const int bRow = warpC * 32 + (lane & 7) + ((lane >> 4) << 3);
    const int bCol = ((lane >> 3) & 1) * 8;
    const uint32_t aAddr0 = smBase + (uint32_t)aRow * 80 + (uint32_t)aCol * 2;
    const uint32_t bAddr0 = smBase + 20480u + (uint32_t)bRow * 80 + (uint32_t)bCol * 2;

    float acc[4][4][4];
#pragma unroll
    for (int i = 0; i < 4; ++i)
#pragma unroll
        for (int j = 0; j < 4; ++j)
#pragma unroll
            for (int v = 0; v < 4; ++v) acc[i][j][v] = 0.f;

    auto issue = [&](int s, int kt) {
        const uint32_t base = smBase + (uint32_t)s * 40960u;
#pragma unroll
        for (int sp = 0; sp < 2; ++sp) {
            const __nv_bfloat16* a = (sp ? Alo : Ahi)
                + (long)(rowBase + cpRow) * K2 + kt * 32;
            uint32_t dA = base + (uint32_t)sp * 10240u + (uint32_t)cpRow * 80 + cpOff;
            cp16(dA, (const char*)a + cpOff);
            cp16(dA + 16, (const char*)a + cpOff + 16);
            const __nv_bfloat16* b = (sp ? Wlo : Whi)
                + (long)(colBase + cpRow) * K2 + kt * 32;
            uint32_t dB = base + 20480u + (uint32_t)sp * 10240u
                          + (uint32_t)cpRow * 80 + cpOff;
            cp16(dB, (const char*)b + cpOff);
            cp16(dB + 16, (const char*)b + cpOff + 16);
        }
    };

    issue(0, 0);
    CP_COMMIT();

    for (int kt = 0; kt < NT; ++kt) {
        const int s = kt & 1;
        if (kt + 1 < NT) {
            issue(s ^ 1, kt + 1);
            CP_COMMIT();
            CP_WAIT1();
        } else {
            CP_WAIT0();
        }
        __syncthreads();

        const uint32_t stA = aAddr0 + (uint32_t)s * 40960u;
        const uint32_t stB = bAddr0 + (uint32_t)s * 40960u;
#pragma unroll
        for (int ks = 0; ks < 2; ++ks) {
            const uint32_t ksOff = (uint32_t)ks * 32;
            uint32_t bh[4][2], bl[4][2];
#pragma unroll
            for (int nfp = 0; nfp < 2; ++nfp) {
                uint32_t bd = stB + (uint32_t)nfp * 1280 + ksOff;
                ldmatrix_x4(bh[nfp * 2][0], bh[nfp * 2][1],
                            bh[nfp * 2 + 1][0], bh[nfp * 2 + 1][1], bd);
                ldmatrix_x4(bl[nfp * 2][0], bl[nfp * 2][1],
                            bl[nfp * 2 + 1][0], bl[nfp * 2 + 1][1], bd + 10240u);
            }
#pragma unroll
            for (int mf = 0; mf < 4; ++mf) {
                uint32_t ah[4], al[4];
                uint32_t ad = stA + (uint32_t)mf * 1280 + ksOff;
                ldmatrix_x4(ah[0], ah[1], ah[2], ah[3], ad);
                ldmatrix_x4(al[0], al[1], al[2], al[3], ad + 10240u);
#pragma unroll
                for (int nf = 0; nf < 4; ++nf) {
                    float* c = acc[mf][nf];
                    mma_bf16(c[0], c[1], c[2], c[3],
                             ah[0], ah[1], ah[2], ah[3], bh[nf][0], bh[nf][1]);
                    mma_bf16(c[0], c[1], c[2], c[3],
                             ah[0], ah[1], ah[2], ah[3], bl[nf][0], bl[nf][1]);
                    mma_bf16(c[0], c[1], c[2], c[3],
                             al[0], al[1], al[2], al[3], bh[nf][0], bh[nf][1]);
                }
            }
        }
        __syncthreads();
    }

    // ---- epilogue ----
    const int gr = lane >> 2;
    const int gc = (lane & 3) * 2;
#pragma unroll
    for (int mf = 0; mf < 4; ++mf) {
#pragma unroll
        for (int nf = 0; nf < 4; ++nf) {
            int col = colBase + warpC * 32 + nf * 8 + gc;
            float b0 = bias[col], b1 = bias[col + 1];
            int row0 = rowBase + warpR * 64 + mf * 16 + gr;
            float* c = acc[mf][nf];
            float2 o0 = make_float2(c[0] + b0, c[1] + b1);
            float2 o1 = make_float2(c[2] + b0, c[3] + b1);
            if (relu) {
                o0.x = fmaxf(o0.x, 0.f); o0.y = fmaxf(o0.y, 0.f);
                o1.x = fmaxf(o1.x, 0.f); o1.y = fmaxf(o1.y, 0.f);
            }
            *(float2*)(C + (long)row0 * Ntot + col) = o0;
            *(float2*)(C + (long)(row0 + 8) * Ntot + col) = o1;
        }
    }
}

// ---------------- layer 2: dual GEMV + log_softmax ----------------
__global__ void layer2_kernel(const float* __restrict__ aggr2,
                              const float* __restrict__ cnt2,
                              const float* __restrict__ h2,
                              const float* __restrict__ Wl2,
                              const float* __restrict__ Wr2,
                              const float* __restrict__ b2,
                              float* __restrict__ out) {
    __shared__ float a[2 * DHv];
    __shared__ float c[DOUTv];
    __shared__ float lse;

    int row = blockIdx.x;
    int tid = threadIdx.x;
    float invc = 1.0f / fmaxf(cnt2[row], 1.0f);
    a[tid] = aggr2[(long)row * DHv + tid] * invc;
    a[DHv + tid] = h2[(long)row * DHv + tid];
    __syncthreads();

    if (tid < DOUTv) {
        float s = b2[tid];
#pragma unroll 8
        for (int k = 0; k < DHv; ++k)
            s = fmaf(a[k], __ldg(&Wl2[k * DOUTv + tid]), s);
#pragma unroll 8
        for (int k = 0; k < DHv; ++k)
            s = fmaf(a[DHv + k], __ldg(&Wr2[k * DOUTv + tid]), s);
        c[tid] = s;
    }
    __syncthreads();

    if (tid == 0) {
        float m = c[0];
#pragma unroll
        for (int j = 1; j < DOUTv; ++j) m = fmaxf(m, c[j]);
        float sum = 0.f;
#pragma unroll
        for (int j = 0; j < DOUTv; ++j) sum += expf(c[j] - m);
        lse = m + logf(sum);
    }
    __syncthreads();

    if (tid < DOUTv) out[(long)row * DOUTv + tid] = c[tid] - lse;
}

// ---------------- host launcher ----------------
extern "C" void kernel_launch(void* const* d_in, const int* in_sizes, int n_in,
                              void* d_out, int out_size) {
    const float* x   = (const float*)d_in[0];
    const int* src0  = (const int*)d_in[1];
    const int* dst0  = (const int*)d_in[2];
    const int* src1  = (const int*)d_in[3];
    const int* dst1  = (const int*)d_in[4];
    const int* src2  = (const int*)d_in[5];
    const int* dst2  = (const int*)d_in[6];
    const float* Wl0 = (const float*)d_in[7];
    const float* bl0 = (const float*)d_in[8];
    const float* Wr0 = (const float*)d_in[9];
    const float* Wl1 = (const float*)d_in[10];
    const float* bl1 = (const float*)d_in[11];
    const float* Wr1 = (const float*)d_in[12];
    const float* Wl2 = (const float*)d_in[13];
    const float* bl2 = (const float*)d_in[14];
    const float* Wr2 = (const float*)d_in[15];
    float* out = (float*)d_out;

    float *aggr0, *cnt0, *h1, *aggr1, *cnt1, *h2, *aggr2, *cnt2;
    __nv_bfloat16 *Ahi, *Alo, *Whi, *Wlo;
    cudaGetSymbolAddress((void**)&aggr0, g_aggr0);
    cudaGetSymbolAddress((void**)&cnt0,  g_cnt0);
    cudaGetSymbolAddress((void**)&h1,    g_h1);
    cudaGetSymbolAddress((void**)&aggr1, g_aggr1);
    cudaGetSymbolAddress((void**)&cnt1,  g_cnt1);
    cudaGetSymbolAddress((void**)&h2,    g_h2);
    cudaGetSymbolAddress((void**)&aggr2, g_aggr2);
    cudaGetSymbolAddress((void**)&cnt2,  g_cnt2);
    cudaGetSymbolAddress((void**)&Ahi,   g_Ahi);
    cudaGetSymbolAddress((void**)&Alo,   g_Alo);
    cudaGetSymbolAddress((void**)&Whi,   g_Whi);
    cudaGetSymbolAddress((void**)&Wlo,   g_Wlo);

    const int smemG = 81920;
    cudaFuncSetAttribute(mma_gemm2_kernel<256>,
                         cudaFuncAttributeMaxDynamicSharedMemorySize, smemG);
    cudaFuncSetAttribute(mma_gemm2_kernel<512>,
                         cudaFuncAttributeMaxDynamicSharedMemorySize, smemG);

    auto zero = [](float* p, long n) {
        int n4 = (int)(n / 4);
        zero_kernel<<<(n4 + 255) / 256, 256>>>((float4*)p, n4);
    };

    // ----- layer 0 -----
    zero(aggr0, (long)N1v * DINv);
    zero(cnt0, N1v);
    convert_W_kernel<<<(256 * 256) / 256, 256>>>(Wl0, Wr0, Whi, Wlo, DINv, DHv);
    edge_agg_kernel<32, 4><<<E0v / 4 / 8, 256>>>(x, src0, dst0, aggr0, cnt0, E0v);
    convert_A_kernel<DINv><<<(int)(((long)N1v * 256 / 4) / 256), 256>>>(
        aggr0, cnt0, x, Ahi, Alo);
    mma_gemm2_kernel<256><<<dim3(N1v / 128, 2), 256, smemG>>>(
        Ahi, Alo, Whi, Wlo, bl0, h1, DHv, 1);

    // ----- layer 1 -----
    zero(aggr1, (long)N2v * DHv);
    zero(cnt1, N2v);
    convert_W_kernel<<<(256 * 512) / 256, 256>>>(Wl1, Wr1, Whi, Wlo, DHv, DHv);
    edge_agg_kernel<64, 4><<<E1v / 4 / 8, 256>>>(h1, src1, dst1, aggr1, cnt1, E1v);
    convert_A_kernel<DHv><<<(int)(((long)N2v * 512 / 4) / 256), 256>>>(
        aggr1, cnt1, h1, Ahi, Alo);
    mma_gemm2_kernel<512><<<dim3(N2v / 128, 2), 256, smemG>>>(
        Ahi, Alo, Whi, Wlo, bl1, h2, DHv, 1);

    // ----- layer 2 + log_softmax -----
    zero(aggr2, (long)N3v * DHv);
    zero(cnt2, N3v);
    edge_agg_kernel<64, 4><<<E2v / 4 / 8, 256>>>(h2, src2, dst2, aggr2, cnt2, E2v);
    layer2_kernel<<<N3v, 256>>>(aggr2, cnt2, h2, Wl2, Wr2, bl2, out);

    (void)in_sizes; (void)n_in; (void)out_size;
}

// round 6
// speedup vs baseline: 1.9045x; 1.0517x over previous
#include <cuda_runtime.h>
#include <cuda_bf16.h>
#include <cstdint>

// ---------------- problem constants ----------------
#define N0v 1000000
#define N1v 102400
#define N2v 10240
#define N3v 1024
#define E0v 1024000
#define E1v 102400
#define E2v 10240
#define DINv 128
#define DHv  256
#define DOUTv 40

// ---------------- device scratch ----------------
__device__ float g_h1[(long)N1v * DHv];
__device__ float g_aggr1[N2v * DHv];
__device__ float g_cnt1[N2v];
__device__ float g_h2[N2v * DHv];
__device__ float g_aggr2[N3v * DHv];
__device__ float g_cnt2[N3v];
__device__ __nv_bfloat16 g_Ahi[(long)N1v * 256];
__device__ __nv_bfloat16 g_Alo[(long)N1v * 256];
__device__ __nv_bfloat16 g_Whi[256 * 512];
__device__ __nv_bfloat16 g_Wlo[256 * 512];
// CSR scratch for layer-0 aggregation
__device__ int g_cnt0i[N1v];
__device__ int g_part[N1v];
__device__ int g_bsums[128];
__device__ int g_start[N1v];
__device__ int g_cursor[N1v];
__device__ int g_csr[E0v];

// ---------------- asm helpers ----------------
__device__ __forceinline__ uint32_t smem_u32(const void* p) {
    uint32_t a;
    asm("{ .reg .u64 t; cvta.to.shared.u64 t, %1; cvt.u32.u64 %0, t; }"
        : "=r"(a) : "l"(p));
    return a;
}
__device__ __forceinline__ void ldmatrix_x4(uint32_t& r0, uint32_t& r1,
                                            uint32_t& r2, uint32_t& r3,
                                            uint32_t addr) {
    asm volatile("ldmatrix.sync.aligned.m8n8.x4.shared.b16 {%0,%1,%2,%3}, [%4];"
                 : "=r"(r0), "=r"(r1), "=r"(r2), "=r"(r3) : "r"(addr));
}
__device__ __forceinline__ void mma_bf16(float& c0, float& c1, float& c2, float& c3,
                                         uint32_t a0, uint32_t a1, uint32_t a2,
                                         uint32_t a3, uint32_t b0, uint32_t b1) {
    asm volatile(
        "mma.sync.aligned.m16n8k16.row.col.f32.bf16.bf16.f32 "
        "{%0,%1,%2,%3},{%4,%5,%6,%7},{%8,%9},{%0,%1,%2,%3};"
        : "+f"(c0), "+f"(c1), "+f"(c2), "+f"(c3)
        : "r"(a0), "r"(a1), "r"(a2), "r"(a3), "r"(b0), "r"(b1));
}
__device__ __forceinline__ void cp16(uint32_t dst, const void* src) {
    asm volatile("cp.async.cg.shared.global [%0], [%1], 16;"
                 :: "r"(dst), "l"(src));
}
#define CP_COMMIT() asm volatile("cp.async.commit_group;")
#define CP_WAIT0()  asm volatile("cp.async.wait_group 0;")
#define CP_WAIT1()  asm volatile("cp.async.wait_group 1;")

__device__ __forceinline__ void red_add_v4(float* p, float4 v) {
    asm volatile("red.global.add.v4.f32 [%0], {%1, %2, %3, %4};"
                 :: "l"(p), "f"(v.x), "f"(v.y), "f"(v.z), "f"(v.w) : "memory");
}

// ---------------- zero ----------------
__global__ void zero_kernel(float4* __restrict__ p, int n4) {
    int i = blockIdx.x * blockDim.x + threadIdx.x;
    if (i < n4) p[i] = make_float4(0.f, 0.f, 0.f, 0.f);
}
__global__ void zero_int_kernel(int4* __restrict__ p, int n4) {
    int i = blockIdx.x * blockDim.x + threadIdx.x;
    if (i < n4) p[i] = make_int4(0, 0, 0, 0);
}

// ---------------- CSR build: hist -> scan -> scatter ----------------
__global__ void hist_kernel(const int* __restrict__ dst, int* __restrict__ cnt,
                            int E) {
    int i = blockIdx.x * blockDim.x + threadIdx.x;
    if (i < E) atomicAdd(&cnt[__ldg(&dst[i])], 1);
}

// block-wise inclusive scan over 1024-element chunks
__global__ void scan_a_kernel(const int* __restrict__ cnt,
                              int* __restrict__ part,
                              int* __restrict__ bsums) {
    __shared__ int sh[1024];
    int tid = threadIdx.x;
    int i = blockIdx.x * 1024 + tid;
    sh[tid] = cnt[i];
    __syncthreads();
#pragma unroll
    for (int d = 1; d < 1024; d <<= 1) {
        int t = (tid >= d) ? sh[tid - d] : 0;
        __syncthreads();
        sh[tid] += t;
        __syncthreads();
    }
    part[i] = sh[tid];
    if (tid == 1023) bsums[blockIdx.x] = sh[tid];
}

// add block offsets, emit exclusive starts + scatter cursors
__global__ void scan_b_kernel(const int* __restrict__ part,
                              const int* __restrict__ bsums,
                              const int* __restrict__ cnt,
                              int* __restrict__ start,
                              int* __restrict__ cursor) {
    __shared__ int off;
    int tid = threadIdx.x;
    if (tid == 0) {
        int s = 0;
        for (int b = 0; b < blockIdx.x; ++b) s += bsums[b];
        off = s;
    }
    __syncthreads();
    int i = blockIdx.x * 1024 + tid;
    int excl = part[i] + off - cnt[i];
    start[i] = excl;
    cursor[i] = excl;
}

__global__ void scatter_kernel(const int* __restrict__ src,
                               const int* __restrict__ dst,
                               int* __restrict__ cursor,
                               int* __restrict__ csr, int E) {
    int i = blockIdx.x * blockDim.x + threadIdx.x;
    if (i < E) {
        int pos = atomicAdd(&cursor[__ldg(&dst[i])], 1);
        csr[pos] = __ldg(&src[i]);
    }
}

// ---------------- bf16 split helper ----------------
__device__ __forceinline__ void split2(float x, float y,
                                       uint32_t& hi, uint32_t& lo) {
    __nv_bfloat16 hx = __float2bfloat16(x);
    __nv_bfloat16 hy = __float2bfloat16(y);
    __nv_bfloat162 hp{hx, hy};
    __nv_bfloat162 lp{__float2bfloat16(x - __bfloat162float(hx)),
                      __float2bfloat16(y - __bfloat162float(hy))};
    hi = *reinterpret_cast<uint32_t*>(&hp);
    lo = *reinterpret_cast<uint32_t*>(&lp);
}

// ---------------- L0 gather-mean: warp per dst, writes bf16 A left half ----
// x rows are 128 floats = 32 float4; lane owns float4 #lane.
__global__ void gather_mean_kernel(const float* __restrict__ x,
                                   const int* __restrict__ csr,
                                   const int* __restrict__ start,
                                   const int* __restrict__ cnt,
                                   __nv_bfloat16* __restrict__ Ahi,
                                   __nv_bfloat16* __restrict__ Alo) {
    int w = blockIdx.x * 8 + (threadIdx.x >> 5);
    int lane = threadIdx.x & 31;
    int beg = __ldg(&start[w]);
    int c = __ldg(&cnt[w]);
    const float4* x4 = reinterpret_cast<const float4*>(x);

    float4 acc = make_float4(0.f, 0.f, 0.f, 0.f);
    int e = 0;
    for (; e + 4 <= c; e += 4) {
        int s0 = __ldg(&csr[beg + e]);
        int s1 = __ldg(&csr[beg + e + 1]);
        int s2 = __ldg(&csr[beg + e + 2]);
        int s3 = __ldg(&csr[beg + e + 3]);
        float4 v0 = __ldcs(&x4[(long)s0 * 32 + lane]);
        float4 v1 = __ldcs(&x4[(long)s1 * 32 + lane]);
        float4 v2 = __ldcs(&x4[(long)s2 * 32 + lane]);
        float4 v3 = __ldcs(&x4[(long)s3 * 32 + lane]);
        acc.x += v0.x + v1.x + v2.x + v3.x;
        acc.y += v0.y + v1.y + v2.y + v3.y;
        acc.z += v0.z + v1.z + v2.z + v3.z;
        acc.w += v0.w + v1.w + v2.w + v3.w;
    }
    for (; e < c; ++e) {
        int s0 = __ldg(&csr[beg + e]);
        float4 v0 = __ldcs(&x4[(long)s0 * 32 + lane]);
        acc.x += v0.x; acc.y += v0.y; acc.z += v0.z; acc.w += v0.w;
    }
    float inv = 1.0f / fmaxf((float)c, 1.0f);
    acc.x *= inv; acc.y *= inv; acc.z *= inv; acc.w *= inv;

    uint32_t h0, l0, h1, l1;
    split2(acc.x, acc.y, h0, l0);
    split2(acc.z, acc.w, h1, l1);
    long o = (long)w * 256 + lane * 4;
    *(uint2*)(Ahi + o) = make_uint2(h0, h1);
    *(uint2*)(Alo + o) = make_uint2(l0, l1);
}

// ---------------- L0 target half: x -> bf16 right half of A ----------------
__global__ void convert_tgt_kernel(const float* __restrict__ x,
                                   __nv_bfloat16* __restrict__ Ahi,
                                   __nv_bfloat16* __restrict__ Alo) {
    long idx = (long)blockIdx.x * blockDim.x + threadIdx.x;
    int r = (int)(idx >> 5);
    int col = (int)(idx & 31) * 4;
    float4 v = *(const float4*)(x + (long)r * 128 + col);
    uint32_t h0, l0, h1, l1;
    split2(v.x, v.y, h0, l0);
    split2(v.z, v.w, h1, l1);
    long o = (long)r * 256 + 128 + col;
    *(uint2*)(Ahi + o) = make_uint2(h0, h1);
    *(uint2*)(Alo + o) = make_uint2(l0, l1);
}

// ---------------- edge aggregation (layers 1-2): red.v4 path ----------------
template <int V4, int EPW>
__global__ void edge_agg_kernel(const float* __restrict__ H,
                                const int* __restrict__ src,
                                const int* __restrict__ dst,
                                float* __restrict__ aggr,
                                float* __restrict__ cnt, int E) {
    constexpr int J = V4 / 32;
    int w = (blockIdx.x * blockDim.x + threadIdx.x) >> 5;
    int lane = threadIdx.x & 31;
    long e0 = (long)w * EPW;
    if (e0 >= E) return;

    int sv = 0, dv = 0;
    if (lane < EPW) {
        sv = __ldg(&src[e0 + lane]);
        dv = __ldg(&dst[e0 + lane]);
    }
    float4 vals[EPW][J];
    int dIdx[EPW];
#pragma unroll
    for (int i = 0; i < EPW; ++i) {
        int s = __shfl_sync(0xffffffffu, sv, i);
        dIdx[i] = __shfl_sync(0xffffffffu, dv, i);
        const float4* sp = reinterpret_cast<const float4*>(H) + (long)s * V4;
#pragma unroll
        for (int j = 0; j < J; ++j)
            vals[i][j] = __ldcs(&sp[lane + j * 32]);
    }
#pragma unroll
    for (int i = 0; i < EPW; ++i) {
        float* dp = aggr + (long)dIdx[i] * (V4 * 4);
#pragma unroll
        for (int j = 0; j < J; ++j)
            red_add_v4(dp + (lane + j * 32) * 4, vals[i][j]);
    }
    if (lane < EPW) atomicAdd(cnt + dv, 1.0f);
}

// ---------------- A2 = [aggr*rn | tgt] -> bf16 hi/lo (layer 1) -------------
template <int KA>
__global__ void convert_A_kernel(const float* __restrict__ aggr,
                                 const float* __restrict__ cnt,
                                 const float* __restrict__ tgt,
                                 __nv_bfloat16* __restrict__ Ahi,
                                 __nv_bfloat16* __restrict__ Alo) {
    constexpr int C4 = KA / 2;
    long idx = (long)blockIdx.x * blockDim.x + threadIdx.x;
    int r = (int)(idx / C4);
    int col = (int)(idx % C4) * 4;
    float4 v;
    if (col < KA) {
        float s = 1.0f / fmaxf(__ldg(&cnt[r]), 1.0f);
        v = *(const float4*)(aggr + (long)r * KA + col);
        v.x *= s; v.y *= s; v.z *= s; v.w *= s;
    } else {
        v = *(const float4*)(tgt + (long)r * KA + (col - KA));
    }
    uint32_t h0, l0, h1, l1;
    split2(v.x, v.y, h0, l0);
    split2(v.z, v.w, h1, l1);
    long o = (long)r * (2 * KA) + col;
    *(uint2*)(Ahi + o) = make_uint2(h0, h1);
    *(uint2*)(Alo + o) = make_uint2(l0, l1);
}

// ---------------- W2T[n][k2] ----------------
__global__ void convert_W_kernel(const float* __restrict__ Wl,
                                 const float* __restrict__ Wr,
                                 __nv_bfloat16* __restrict__ Whi,
                                 __nv_bfloat16* __restrict__ Wlo,
                                 int KA, int N) {
    int idx = blockIdx.x * blockDim.x + threadIdx.x;
    int n = idx % N;
    int k2 = idx / N;
    float w = (k2 < KA) ? __ldg(&Wl[(long)k2 * N + n])
                        : __ldg(&Wr[(long)(k2 - KA) * N + n]);
    __nv_bfloat16 h = __float2bfloat16(w);
    __nv_bfloat16 l = __float2bfloat16(w - __bfloat162float(h));
    Whi[(long)n * (2 * KA) + k2] = h;
    Wlo[(long)n * (2 * KA) + k2] = l;
}

// ---------------- bf16-split GEMM (grid = (Ncols, Mrows) for A L2-reuse) ---
template <int K2>
__global__ __launch_bounds__(256, 2)
void mma_gemm2_kernel(const __nv_bfloat16* __restrict__ Ahi,
                      const __nv_bfloat16* __restrict__ Alo,
                      const __nv_bfloat16* __restrict__ Whi,
                      const __nv_bfloat16* __restrict__ Wlo,
                      const float* __restrict__ bias,
                      float* __restrict__ C,
                      int Ntot, int relu) {
    constexpr int NT = K2 / 32;
    extern __shared__ __align__(16) __nv_bfloat16 sm[];
    const uint32_t smBase = smem_u32(sm);

    const int tid = threadIdx.x;
    const int lane = tid & 31;
    const int wid = tid >> 5;
    const int warpR = wid & 1;
    const int warpC = wid >> 1;
    const int rowBase = blockIdx.y * 128;   // row block (outer)
    const int colBase = blockIdx.x * 128;   // col block (adjacent -> A reuse)

    const int cpRow = tid >> 1;
    const int cpOff = (tid & 1) * 32;

    const int aRow = warpR * 64 + (lane & 15);
    const int aCol = (lane >> 4) * 8;
    const int bRow = warpC * 32 + (lane & 7) + ((lane >> 4) << 3);
    const int bCol = ((lane >> 3) & 1) * 8;
    const uint32_t aAddr0 = smBase + (uint32_t)aRow * 80 + (uint32_t)aCol * 2;
    const uint32_t bAddr0 = smBase + 20480u + (uint32_t)bRow * 80 + (uint32_t)bCol * 2;

    float acc[4][4][4];
#pragma unroll
    for (int i = 0; i < 4; ++i)
#pragma unroll
        for (int j = 0; j < 4; ++j)
#pragma unroll
            for (int v = 0; v < 4; ++v) acc[i][j][v] = 0.f;

    auto issue = [&](int s, int kt) {
        const uint32_t base = smBase + (uint32_t)s * 40960u;
#pragma unroll
        for (int sp = 0; sp < 2; ++sp) {
            const __nv_bfloat16* a = (sp ? Alo : Ahi)
                + (long)(rowBase + cpRow) * K2 + kt * 32;
            uint32_t dA = base + (uint32_t)sp * 10240u + (uint32_t)cpRow * 80 + cpOff;
            cp16(dA, (const char*)a + cpOff);
            cp16(dA + 16, (const char*)a + cpOff + 16);
            const __nv_bfloat16* b = (sp ? Wlo : Whi)
                + (long)(colBase + cpRow) * K2 + kt * 32;
            uint32_t dB = base + 20480u + (uint32_t)sp * 10240u
                          + (uint32_t)cpRow * 80 + cpOff;
            cp16(dB, (const char*)b + cpOff);
            cp16(dB + 16, (const char*)b + cpOff + 16);
        }
    };

    issue(0, 0);
    CP_COMMIT();

    for (int kt = 0; kt < NT; ++kt) {
        const int s = kt & 1;
        if (kt + 1 < NT) {
            issue(s ^ 1, kt + 1);
            CP_COMMIT();
            CP_WAIT1();
        } else {
            CP_WAIT0();
        }
        __syncthreads();

        const uint32_t stA = aAddr0 + (uint32_t)s * 40960u;
        const uint32_t stB = bAddr0 + (uint32_t)s * 40960u;
#pragma unroll
        for (int ks = 0; ks < 2; ++ks) {
            const uint32_t ksOff = (uint32_t)ks * 32;
            uint32_t bh[4][2], bl[4][2];
#pragma unroll
            for (int nfp = 0; nfp < 2; ++nfp) {
                uint32_t bd = stB + (uint32_t)nfp * 1280 + ksOff;
                ldmatrix_x4(bh[nfp * 2][0], bh[nfp * 2][1],
                            bh[nfp * 2 + 1][0], bh[nfp * 2 + 1][1], bd);
                ldmatrix_x4(bl[nfp * 2][0], bl[nfp * 2][1],
                            bl[nfp * 2 + 1][0], bl[nfp * 2 + 1][1], bd + 10240u);
            }
#pragma unroll
            for (int mf = 0; mf < 4; ++mf) {
                uint32_t ah[4], al[4];
                uint32_t ad = stA + (uint32_t)mf * 1280 + ksOff;
                ldmatrix_x4(ah[0], ah[1], ah[2], ah[3], ad);
                ldmatrix_x4(al[0], al[1], al[2], al[3], ad + 10240u);
#pragma unroll
                for (int nf = 0; nf < 4; ++nf) {
                    float* c = acc[mf][nf];
                    mma_bf16(c[0], c[1], c[2], c[3],
                             ah[0], ah[1], ah[2], ah[3], bh[nf][0], bh[nf][1]);
                    mma_bf16(c[0], c[1], c[2], c[3],
                             ah[0], ah[1], ah[2], ah[3], bl[nf][0], bl[nf][1]);
                    mma_bf16(c[0], c[1], c[2], c[3],
                             al[0], al[1], al[2], al[3], bh[nf][0], bh[nf][1]);
                }
            }
        }
        __syncthreads();
    }

    const int gr = lane >> 2;
    const int gc = (lane & 3) * 2;
#pragma unroll
    for (int mf = 0; mf < 4; ++mf) {
#pragma unroll
        for (int nf = 0; nf < 4; ++nf) {
            int col = colBase + warpC * 32 + nf * 8 + gc;
            float b0 = bias[col], b1 = bias[col + 1];
            int row0 = rowBase + warpR * 64 + mf * 16 + gr;
            float* c = acc[mf][nf];
            float2 o0 = make_float2(c[0] + b0, c[1] + b1);
            float2 o1 = make_float2(c[2] + b0, c[3] + b1);
            if (relu) {
                o0.x = fmaxf(o0.x, 0.f); o0.y = fmaxf(o0.y, 0.f);
                o1.x = fmaxf(o1.x, 0.f); o1.y = fmaxf(o1.y, 0.f);
            }
            *(float2*)(C + (long)row0 * Ntot + col) = o0;
            *(float2*)(C + (long)(row0 + 8) * Ntot + col) = o1;
        }
    }
}

// ---------------- layer 2: dual GEMV + log_softmax ----------------
__global__ void layer2_kernel(const float* __restrict__ aggr2,
                              const float* __restrict__ cnt2,
                              const float* __restrict__ h2,
                              const float* __restrict__ Wl2,
                              const float* __restrict__ Wr2,
                              const float* __restrict__ b2,
                              float* __restrict__ out) {
    __shared__ float a[2 * DHv];
    __shared__ float c[DOUTv];
    __shared__ float lse;

    int row = blockIdx.x;
    int tid = threadIdx.x;
    float invc = 1.0f / fmaxf(cnt2[row], 1.0f);
    a[tid] = aggr2[(long)row * DHv + tid] * invc;
    a[DHv + tid] = h2[(long)row * DHv + tid];
    __syncthreads();

    if (tid < DOUTv) {
        float s = b2[tid];
#pragma unroll 8
        for (int k = 0; k < DHv; ++k)
            s = fmaf(a[k], __ldg(&Wl2[k * DOUTv + tid]), s);
#pragma unroll 8
        for (int k = 0; k < DHv; ++k)
            s = fmaf(a[DHv + k], __ldg(&Wr2[k * DOUTv + tid]), s);
        c[tid] = s;
    }
    __syncthreads();

    if (tid == 0) {
        float m = c[0];
#pragma unroll
        for (int j = 1; j < DOUTv; ++j) m = fmaxf(m, c[j]);
        float sum = 0.f;
#pragma unroll
        for (int j = 0; j < DOUTv; ++j) sum += expf(c[j] - m);
        lse = m + logf(sum);
    }
    __syncthreads();

    if (tid < DOUTv) out[(long)row * DOUTv + tid] = c[tid] - lse;
}

// ---------------- host launcher ----------------
extern "C" void kernel_launch(void* const* d_in, const int* in_sizes, int n_in,
                              void* d_out, int out_size) {
    const float* x   = (const float*)d_in[0];
    const int* src0  = (const int*)d_in[1];
    const int* dst0  = (const int*)d_in[2];
    const int* src1  = (const int*)d_in[3];
    const int* dst1  = (const int*)d_in[4];
    const int* src2  = (const int*)d_in[5];
    const int* dst2  = (const int*)d_in[6];
    const float* Wl0 = (const float*)d_in[7];
    const float* bl0 = (const float*)d_in[8];
    const float* Wr0 = (const float*)d_in[9];
    const float* Wl1 = (const float*)d_in[10];
    const float* bl1 = (const float*)d_in[11];
    const float* Wr1 = (const float*)d_in[12];
    const float* Wl2 = (const float*)d_in[13];
    const float* bl2 = (const float*)d_in[14];
    const float* Wr2 = (const float*)d_in[15];
    float* out = (float*)d_out;

    float *h1, *aggr1, *cnt1, *h2, *aggr2, *cnt2;
    __nv_bfloat16 *Ahi, *Alo, *Whi, *Wlo;
    int *cnt0i, *part, *bsums, *startp, *cursor, *csr;
    cudaGetSymbolAddress((void**)&h1,    g_h1);
    cudaGetSymbolAddress((void**)&aggr1, g_aggr1);
    cudaGetSymbolAddress((void**)&cnt1,  g_cnt1);
    cudaGetSymbolAddress((void**)&h2,    g_h2);
    cudaGetSymbolAddress((void**)&aggr2, g_aggr2);
    cudaGetSymbolAddress((void**)&cnt2,  g_cnt2);
    cudaGetSymbolAddress((void**)&Ahi,   g_Ahi);
    cudaGetSymbolAddress((void**)&Alo,   g_Alo);
    cudaGetSymbolAddress((void**)&Whi,   g_Whi);
    cudaGetSymbolAddress((void**)&Wlo,   g_Wlo);
    cudaGetSymbolAddress((void**)&cnt0i, g_cnt0i);
    cudaGetSymbolAddress((void**)&part,  g_part);
    cudaGetSymbolAddress((void**)&bsums, g_bsums);
    cudaGetSymbolAddress((void**)&startp,g_start);
    cudaGetSymbolAddress((void**)&cursor,g_cursor);
    cudaGetSymbolAddress((void**)&csr,   g_csr);

    const int smemG = 81920;
    cudaFuncSetAttribute(mma_gemm2_kernel<256>,
                         cudaFuncAttributeMaxDynamicSharedMemorySize, smemG);
    cudaFuncSetAttribute(mma_gemm2_kernel<512>,
                         cudaFuncAttributeMaxDynamicSharedMemorySize, smemG);

    auto zero = [](float* p, long n) {
        int n4 = (int)(n / 4);
        zero_kernel<<<(n4 + 255) / 256, 256>>>((float4*)p, n4);
    };

    // ----- layer 0 (CSR aggregation, no atomic feature traffic) -----
    zero_int_kernel<<<(N1v / 4 + 255) / 256, 256>>>((int4*)cnt0i, N1v / 4);
    hist_kernel<<<E0v / 256, 256>>>(dst0, cnt0i, E0v);
    scan_a_kernel<<<N1v / 1024, 1024>>>(cnt0i, part, bsums);
    scan_b_kernel<<<N1v / 1024, 1024>>>(part, bsums, cnt0i, startp, cursor);
    scatter_kernel<<<E0v / 256, 256>>>(src0, dst0, cursor, csr, E0v);
    gather_mean_kernel<<<N1v / 8, 256>>>(x, csr, startp, cnt0i, Ahi, Alo);
    convert_W_kernel<<<(256 * 256) / 256, 256>>>(Wl0, Wr0, Whi, Wlo, DINv, DHv);
    convert_tgt_kernel<<<(int)(((long)N1v * 32) / 256), 256>>>(x, Ahi, Alo);
    mma_gemm2_kernel<256><<<dim3(2, N1v / 128), 256, smemG>>>(
        Ahi, Alo, Whi, Wlo, bl0, h1, DHv, 1);

    // ----- layer 1 -----
    zero(aggr1, (long)N2v * DHv);
    zero(cnt1, N2v);
    convert_W_kernel<<<(256 * 512) / 256, 256>>>(Wl1, Wr1, Whi, Wlo, DHv, DHv);
    edge_agg_kernel<64, 4><<<E1v / 4 / 8, 256>>>(h1, src1, dst1, aggr1, cnt1, E1v);
    convert_A_kernel<DHv><<<(int)(((long)N2v * 512 / 4) / 256), 256>>>(
        aggr1, cnt1, h1, Ahi, Alo);
    mma_gemm2_kernel<512><<<dim3(2, N2v / 128), 256, smemG>>>(
        Ahi, Alo, Whi, Wlo, bl1, h2, DHv, 1);

    // ----- layer 2 + log_softmax -----
    zero(aggr2, (long)N3v * DHv);
    zero(cnt2, N3v);
    edge_agg_kernel<64, 4><<<E2v / 4 / 8, 256>>>(h2, src2, dst2, aggr2, cnt2, E2v);
    layer2_kernel<<<N3v, 256>>>(aggr2, cnt2, h2, Wl2, Wr2, bl2, out);

    (void)in_sizes; (void)n_in; (void)out_size;
}